// round 12
// baseline (speedup 1.0000x reference)
#include <cuda_runtime.h>
#include <math.h>

#define NTOK 1024   // B*S = 2*512
#define AKS 4       // attention key split

// Scratch (device globals)
__device__ float g_A[3 * 64 * 512];     // folded Pin@W_head
__device__ float g_U[512 * 64];         // folded Wo@Pout_v
__device__ float g_M[64];               // Pout_q^T Pout_k / 8
__device__ float g_ct[8];               // cos(theta_w + theta_{8+w})
__device__ float g_z[3 * 16 * 512 * 8]; // [stream][bh][s][8]
__device__ float g_Yp[AKS * NTOK * 64]; // attn partial sums
__device__ float g_lp[AKS * NTOK * 8];  // attn partial normalizers

__device__ __forceinline__ float ex2(float x) {
    float y;
    asm("ex2.approx.f32 %0, %1;" : "=f"(y) : "f"(x));
    return y;
}

// ---------------------------------------------------------------------------
// Fold kernel. Blocks 0..47: A. Blocks 48..63: U. Block 64: M + ct.
// ---------------------------------------------------------------------------
__global__ __launch_bounds__(256) void k_fold(
    const float* __restrict__ Wq, const float* __restrict__ Wk,
    const float* __restrict__ Wv, const float* __restrict__ Wo,
    const float* __restrict__ Pq, const float* __restrict__ Pk,
    const float* __restrict__ Pv, const float* __restrict__ Poq,
    const float* __restrict__ Pok, const float* __restrict__ Pov,
    const float* __restrict__ theta) {
    __shared__ float sP[512];
    int blk = blockIdx.x;
    int t = threadIdx.x;
    if (blk < 48) {
        int idx = blk * 256 + t;
        int stream = idx >> 12;
        int rem = idx & 4095;
        int h = rem >> 9;
        int e = rem & 511;
        const float* W = (stream == 0) ? Wq : ((stream == 1) ? Wk : Wv);
        const float* P = (stream == 0) ? Pq : ((stream == 1) ? Pk : Pv);
        sP[t] = P[t];
        sP[t + 256] = P[t + 256];
        __syncthreads();
        float acc[8] = {};
#pragma unroll
        for (int d = 0; d < 64; ++d) {
            float w = W[(h * 64 + d) * 512 + e];
#pragma unroll
            for (int q = 0; q < 8; ++q)
                acc[q] = fmaf(sP[q * 64 + d], w, acc[q]);
        }
#pragma unroll
        for (int q = 0; q < 8; ++q)
            g_A[(stream * 64 + h * 8 + q) * 512 + e] = acc[q];
    } else if (blk < 64) {
        int idx = (blk - 48) * 256 + t;
        sP[t] = Pov[t];
        sP[t + 256] = Pov[t + 256];
        __syncthreads();
        int e = idx >> 3, h = idx & 7;
        float acc[8] = {};
#pragma unroll
        for (int d = 0; d < 64; ++d) {
            float w = Wo[e * 512 + h * 64 + d];
#pragma unroll
            for (int q = 0; q < 8; ++q)
                acc[q] = fmaf(w, sP[d * 8 + q], acc[q]);
        }
#pragma unroll
        for (int q = 0; q < 8; ++q)
            g_U[e * 64 + h * 8 + q] = acc[q];
    } else {
        if (t < 64) {
            int i = t >> 3, j = t & 7;
            float acc = 0.f;
#pragma unroll
            for (int d = 0; d < 64; ++d)
                acc = fmaf(Poq[d * 8 + i], Pok[d * 8 + j], acc);
            g_M[t] = acc * 0.125f;
        } else if (t < 72) {
            int w = t - 64;
            g_ct[w] = __cosf(theta[w] + theta[8 + w]);
        }
    }
}

// ---------------------------------------------------------------------------
// FUSED qp-GEMM + z kernel. Tile: 16 tokens x 64 cols (one stream = all 8
// heads x 8 wires for those tokens), full K=512 in-block -> no partials.
// grid (3 streams, 64 token-tiles) = 192 blocks, 128 threads.
// GEMM: BK=32, 2x4 microtile. Tail: cos prefix products + M fold (stream 0).
// ---------------------------------------------------------------------------
__global__ __launch_bounds__(128) void k_qpz(const float* __restrict__ x) {
    __shared__ float As[32 * 17];   // x tile, [k][m], padded
    __shared__ float Bs[32 * 68];   // A tile, [k][n], padded (68 % 4 == 0)
    __shared__ float sq[16 * 68];   // qp result tile
    __shared__ float sM[64];
    __shared__ float sct[8];
    int stream = blockIdx.x;        // 0..2
    int bm = blockIdx.y * 16;       // token base
    int tid = threadIdx.x;
    if (tid < 64) sM[tid] = g_M[tid];
    else if (tid < 72) sct[tid - 64] = g_ct[tid - 64];

    const float* Abase = g_A + stream * 64 * 512;
    int tx = tid & 15, ty = tid >> 4;   // 16 col-groups x 8 row-groups
    float acc[2][4] = {};

    for (int kk = 0; kk < 512; kk += 32) {
        // x tile: 16 rows x 32 k = 512 floats, 1 float4/thread
        {
            int row = tid >> 3;
            int c4 = (tid & 7) * 4;
            float4 v = *(const float4*)(x + (size_t)(bm + row) * 512 + kk + c4);
            As[(c4 + 0) * 17 + row] = v.x;
            As[(c4 + 1) * 17 + row] = v.y;
            As[(c4 + 2) * 17 + row] = v.z;
            As[(c4 + 3) * 17 + row] = v.w;
        }
        // A tile: 64 rows x 32 k = 2048 floats, 4 float4/thread
#pragma unroll
        for (int i = 0; i < 4; ++i) {
            int t2 = tid + i * 128;
            int row = t2 >> 3;
            int c4 = (t2 & 7) * 4;
            float4 v = *(const float4*)(Abase + (size_t)row * 512 + kk + c4);
            Bs[(c4 + 0) * 68 + row] = v.x;
            Bs[(c4 + 1) * 68 + row] = v.y;
            Bs[(c4 + 2) * 68 + row] = v.z;
            Bs[(c4 + 3) * 68 + row] = v.w;
        }
        __syncthreads();
#pragma unroll 8
        for (int k = 0; k < 32; ++k) {
            float a0 = As[k * 17 + ty * 2];
            float a1 = As[k * 17 + ty * 2 + 1];
            float4 bv = *(const float4*)&Bs[k * 68 + tx * 4];
            acc[0][0] = fmaf(a0, bv.x, acc[0][0]);
            acc[0][1] = fmaf(a0, bv.y, acc[0][1]);
            acc[0][2] = fmaf(a0, bv.z, acc[0][2]);
            acc[0][3] = fmaf(a0, bv.w, acc[0][3]);
            acc[1][0] = fmaf(a1, bv.x, acc[1][0]);
            acc[1][1] = fmaf(a1, bv.y, acc[1][1]);
            acc[1][2] = fmaf(a1, bv.z, acc[1][2]);
            acc[1][3] = fmaf(a1, bv.w, acc[1][3]);
        }
        __syncthreads();
    }
    // stash qp tile
#pragma unroll
    for (int j = 0; j < 4; ++j) {
        sq[(ty * 2 + 0) * 68 + tx * 4 + j] = acc[0][j];
        sq[(ty * 2 + 1) * 68 + tx * 4 + j] = acc[1][j];
    }
    __syncthreads();

    // z tail: 128 threads = 16 tokens x 8 heads
    {
        int token = tid >> 3, h = tid & 7;
        float ang[8];
#pragma unroll
        for (int w = 0; w < 8; ++w)
            ang[w] = sq[token * 68 + h * 8 + w];
        float cz[8];
#pragma unroll
        for (int w = 0; w < 8; ++w) cz[w] = __cosf(ang[w]) * sct[w];
        float z[8];
        float p = 1.f;
#pragma unroll
        for (int w = 0; w < 8; ++w) { p *= cz[w]; z[w] = p; }
        float y[8];
        if (stream == 0) {
#pragma unroll
            for (int j = 0; j < 8; ++j) {
                float a = 0.f;
#pragma unroll
                for (int i = 0; i < 8; ++i)
                    a = fmaf(z[i], sM[i * 8 + j], a);
                y[j] = a;
            }
        } else {
#pragma unroll
            for (int j = 0; j < 8; ++j) y[j] = z[j];
        }
        int n = bm + token;
        int b = n >> 9, s = n & 511;
        float* dst = g_z + ((size_t)(stream * 16 + b * 8 + h) * 512 + s) * 8;
        *(float4*)dst = make_float4(y[0], y[1], y[2], y[3]);
        *(float4*)(dst + 4) = make_float4(y[4], y[5], y[6], y[7]);
    }
}

// ---------------------------------------------------------------------------
// Rank-8 attention: 4 independent rows/thread (4 parallel dot->exp->acc
// chains), 8 subs, 4-way key split. grid (8 qt of 64 rows, 16 bh, 4 ks) =
// 512 blocks x 128 threads. ex2.approx (q pre-scaled by log2 e).
// Writes partial (sum p*v, sum p); normalization folded into final GEMM.
// ---------------------------------------------------------------------------
__global__ __launch_bounds__(128) void k_attn9() {
    __shared__ float s_zk[128 * 12];
    __shared__ float s_zv[128 * 12];
    int qt = blockIdx.x, bh = blockIdx.y, ks = blockIdx.z;
    int b = bh >> 3, h = bh & 7;
    int q0 = qt * 64;
    int key0 = ks * 128;
    const float* gzq = g_z + (size_t)bh * 4096;
    const float* gzk = g_z + (size_t)(16 + bh) * 4096 + key0 * 8;
    const float* gzv = g_z + (size_t)(32 + bh) * 4096 + key0 * 8;
    int tid = threadIdx.x;

    {
        int r = tid;   // one key row per thread
        float4 a = ((const float4*)gzk)[r * 2], c = ((const float4*)gzk)[r * 2 + 1];
        *(float4*)(s_zk + r * 12) = a;
        *(float4*)(s_zk + r * 12 + 4) = c;
        float4 e = ((const float4*)gzv)[r * 2], f = ((const float4*)gzv)[r * 2 + 1];
        *(float4*)(s_zv + r * 12) = e;
        *(float4*)(s_zv + r * 12 + 4) = f;
    }
    __syncthreads();

    int rg = tid >> 3, sub = tid & 7;     // 16 rowgroups x 4 rows = 64 rows
    int r0 = q0 + rg * 4;
    const float L2E = 1.4426950408889634f;
    float y[4][8];
#pragma unroll
    for (int r = 0; r < 4; ++r) {
        float4 a = ((const float4*)gzq)[(r0 + r) * 2];
        float4 bq = ((const float4*)gzq)[(r0 + r) * 2 + 1];
        y[r][0] = a.x * L2E; y[r][1] = a.y * L2E; y[r][2] = a.z * L2E; y[r][3] = a.w * L2E;
        y[r][4] = bq.x * L2E; y[r][5] = bq.y * L2E; y[r][6] = bq.z * L2E; y[r][7] = bq.w * L2E;
    }

    float l[4] = {};
    float acc[4][8] = {};
#pragma unroll 4
    for (int it = 0; it < 16; ++it) {
        int key = sub + it * 8;
        float4 k0 = *(const float4*)(s_zk + key * 12);
        float4 k1 = *(const float4*)(s_zk + key * 12 + 4);
        float kr[8] = {k0.x, k0.y, k0.z, k0.w, k1.x, k1.y, k1.z, k1.w};
        float p[4];
#pragma unroll
        for (int r = 0; r < 4; ++r) {
            float s = y[r][0] * kr[0];
#pragma unroll
            for (int j = 1; j < 8; ++j) s = fmaf(y[r][j], kr[j], s);
            p[r] = ex2(s);
            l[r] += p[r];
        }
        float4 v0 = *(const float4*)(s_zv + key * 12);
        float4 v1 = *(const float4*)(s_zv + key * 12 + 4);
        float vr[8] = {v0.x, v0.y, v0.z, v0.w, v1.x, v1.y, v1.z, v1.w};
#pragma unroll
        for (int r = 0; r < 4; ++r)
#pragma unroll
            for (int j = 0; j < 8; ++j)
                acc[r][j] = fmaf(p[r], vr[j], acc[r][j]);
    }
    // reduce over 8 subs (xor d=1,2,4 stays within each 8-lane group)
#pragma unroll
    for (int d = 1; d <= 4; d <<= 1) {
#pragma unroll
        for (int r = 0; r < 4; ++r) {
            l[r] += __shfl_xor_sync(0xffffffffu, l[r], d);
#pragma unroll
            for (int j = 0; j < 8; ++j)
                acc[r][j] += __shfl_xor_sync(0xffffffffu, acc[r][j], d);
        }
    }
    if (sub == 0) {
        float* yp = g_Yp + ks * (NTOK * 64);
        float* lp = g_lp + ks * (NTOK * 8);
#pragma unroll
        for (int r = 0; r < 4; ++r) {
            int n0 = b * 512 + r0 + r;
            float4* o = (float4*)(yp + (size_t)n0 * 64 + h * 8);
            o[0] = make_float4(acc[r][0], acc[r][1], acc[r][2], acc[r][3]);
            o[1] = make_float4(acc[r][4], acc[r][5], acc[r][6], acc[r][7]);
            lp[n0 * 8 + h] = l[r];
        }
    }
}

// ---------------------------------------------------------------------------
// Final GEMM: out = Y(1024x64) @ U(512x64)^T, Y assembled from 4 key-split
// partials: Y = (sum Yp)/(sum lp). Tile 32x64, BK=64, grid (8,32)=256
// blocks, 256 threads, 2x4 microtile.
// ---------------------------------------------------------------------------
__global__ __launch_bounds__(256) void k_gemm_fin(float* __restrict__ C) {
    __shared__ float As[64][32];   // [k][m]
    __shared__ float Bs[64][64];   // [k][n]
    int bm = blockIdx.y * 32, bn = blockIdx.x * 64;
    int tid = threadIdx.x;
    int tx = tid & 15, ty = tid >> 4;

#pragma unroll
    for (int i = 0; i < 2; ++i) {
        int t = tid + i * 256;
        int row = t >> 4;
        int c4 = (t & 15) * 4;
        int n = bm + row;
        int h = c4 >> 3;
        float l = 0.f;
        float sx = 0.f, sy = 0.f, sz = 0.f, sw = 0.f;
#pragma unroll
        for (int ks = 0; ks < AKS; ++ks) {
            l += g_lp[ks * (NTOK * 8) + n * 8 + h];
            float4 p = *(const float4*)(g_Yp + (size_t)ks * (NTOK * 64) + n * 64 + c4);
            sx += p.x; sy += p.y; sz += p.z; sw += p.w;
        }
        float inv = 1.f / l;
        As[c4 + 0][row] = sx * inv;
        As[c4 + 1][row] = sy * inv;
        As[c4 + 2][row] = sz * inv;
        As[c4 + 3][row] = sw * inv;
    }
#pragma unroll
    for (int i = 0; i < 4; ++i) {
        int t = tid + i * 256;
        int row = t >> 4;
        int c4 = (t & 15) * 4;
        float4 v = *(const float4*)(g_U + (size_t)(bn + row) * 64 + c4);
        Bs[c4 + 0][row] = v.x; Bs[c4 + 1][row] = v.y;
        Bs[c4 + 2][row] = v.z; Bs[c4 + 3][row] = v.w;
    }
    __syncthreads();

    float acc[2][4] = {};
#pragma unroll 8
    for (int k = 0; k < 64; ++k) {
        float a0 = As[k][ty * 2];
        float a1 = As[k][ty * 2 + 1];
        float4 bv = *(const float4*)&Bs[k][tx * 4];
        acc[0][0] = fmaf(a0, bv.x, acc[0][0]);
        acc[0][1] = fmaf(a0, bv.y, acc[0][1]);
        acc[0][2] = fmaf(a0, bv.z, acc[0][2]);
        acc[0][3] = fmaf(a0, bv.w, acc[0][3]);
        acc[1][0] = fmaf(a1, bv.x, acc[1][0]);
        acc[1][1] = fmaf(a1, bv.y, acc[1][1]);
        acc[1][2] = fmaf(a1, bv.z, acc[1][2]);
        acc[1][3] = fmaf(a1, bv.w, acc[1][3]);
    }
#pragma unroll
    for (int i = 0; i < 2; ++i) {
        float4 o = make_float4(acc[i][0], acc[i][1], acc[i][2], acc[i][3]);
        *(float4*)(C + (size_t)(bm + ty * 2 + i) * 512 + bn + tx * 4) = o;
    }
}

// ---------------------------------------------------------------------------
extern "C" void kernel_launch(void* const* d_in, const int* in_sizes, int n_in,
                              void* d_out, int out_size) {
    const float* x      = (const float*)d_in[0];
    const float* Wq     = (const float*)d_in[1];
    const float* Wk     = (const float*)d_in[2];
    const float* Wv     = (const float*)d_in[3];
    const float* Wo     = (const float*)d_in[4];
    const float* Pin_q  = (const float*)d_in[5];
    const float* Pin_k  = (const float*)d_in[6];
    const float* Pin_v  = (const float*)d_in[7];
    const float* Pout_q = (const float*)d_in[8];
    const float* Pout_k = (const float*)d_in[9];
    const float* Pout_v = (const float*)d_in[10];
    const float* theta  = (const float*)d_in[11];
    float* out = (float*)d_out;

    k_fold<<<65, 256>>>(Wq, Wk, Wv, Wo, Pin_q, Pin_k, Pin_v,
                        Pout_q, Pout_k, Pout_v, theta);
    k_qpz<<<dim3(3, 64), 128>>>(x);
    k_attn9<<<dim3(8, 16, AKS), 128>>>();
    k_gemm_fin<<<dim3(8, 32), 256>>>(out);
}

// round 13
// speedup vs baseline: 1.4233x; 1.4233x over previous
#include <cuda_runtime.h>
#include <math.h>

#define NTOK 1024   // B*S = 2*512
#define KSPLIT 8    // qp GEMM split-K
#define AKS 4       // attention key split

// Scratch (device globals)
__device__ float g_A[3 * 64 * 512];             // folded Pin@W_head
__device__ float g_U[512 * 64];                 // folded Wo@Pout_v
__device__ float g_M[64];                       // Pout_q^T Pout_k / 8
__device__ float g_ct[8];                       // cos(theta_w + theta_{8+w})
__device__ float g_qp_part[KSPLIT * NTOK * 192];// split-K partials of x@A^T
__device__ float g_z[3 * 16 * 512 * 8];         // [stream][bh][s][8]
__device__ float g_Yp[AKS * NTOK * 64];         // attn partial sums
__device__ float g_lp[AKS * NTOK * 8];          // attn partial normalizers

__device__ __forceinline__ float ex2(float x) {
    float y;
    asm("ex2.approx.f32 %0, %1;" : "=f"(y) : "f"(x));
    return y;
}

// ---------------------------------------------------------------------------
// Fold kernel. Blocks 0..47: A. Blocks 48..63: U. Block 64: M + ct.
// ---------------------------------------------------------------------------
__global__ __launch_bounds__(256) void k_fold(
    const float* __restrict__ Wq, const float* __restrict__ Wk,
    const float* __restrict__ Wv, const float* __restrict__ Wo,
    const float* __restrict__ Pq, const float* __restrict__ Pk,
    const float* __restrict__ Pv, const float* __restrict__ Poq,
    const float* __restrict__ Pok, const float* __restrict__ Pov,
    const float* __restrict__ theta) {
    __shared__ float sP[512];
    int blk = blockIdx.x;
    int t = threadIdx.x;
    if (blk < 48) {
        int idx = blk * 256 + t;
        int stream = idx >> 12;
        int rem = idx & 4095;
        int h = rem >> 9;
        int e = rem & 511;
        const float* W = (stream == 0) ? Wq : ((stream == 1) ? Wk : Wv);
        const float* P = (stream == 0) ? Pq : ((stream == 1) ? Pk : Pv);
        sP[t] = P[t];
        sP[t + 256] = P[t + 256];
        __syncthreads();
        float acc[8] = {};
#pragma unroll
        for (int d = 0; d < 64; ++d) {
            float w = W[(h * 64 + d) * 512 + e];
#pragma unroll
            for (int q = 0; q < 8; ++q)
                acc[q] = fmaf(sP[q * 64 + d], w, acc[q]);
        }
#pragma unroll
        for (int q = 0; q < 8; ++q)
            g_A[(stream * 64 + h * 8 + q) * 512 + e] = acc[q];
    } else if (blk < 64) {
        int idx = (blk - 48) * 256 + t;
        sP[t] = Pov[t];
        sP[t + 256] = Pov[t + 256];
        __syncthreads();
        int e = idx >> 3, h = idx & 7;
        float acc[8] = {};
#pragma unroll
        for (int d = 0; d < 64; ++d) {
            float w = Wo[e * 512 + h * 64 + d];
#pragma unroll
            for (int q = 0; q < 8; ++q)
                acc[q] = fmaf(w, sP[d * 8 + q], acc[q]);
        }
#pragma unroll
        for (int q = 0; q < 8; ++q)
            g_U[e * 64 + h * 8 + q] = acc[q];
    } else {
        if (t < 64) {
            int i = t >> 3, j = t & 7;
            float acc = 0.f;
#pragma unroll
            for (int d = 0; d < 64; ++d)
                acc = fmaf(Poq[d * 8 + i], Pok[d * 8 + j], acc);
            g_M[t] = acc * 0.125f;
        } else if (t < 72) {
            int w = t - 64;
            g_ct[w] = __cosf(theta[w] + theta[8 + w]);
        }
    }
}

// ---------------------------------------------------------------------------
// Split-K GEMM: qp_part[z] = x[:, z*64:(z+1)*64] @ A[:, same]^T
// grid (3, 16, 8) = 384 blocks, 256 threads, 64x64 tile, BK=32, 4x4 microtile
// ---------------------------------------------------------------------------
__global__ __launch_bounds__(256) void k_gemm_qp(const float* __restrict__ A) {
    const float* B = g_A;
    __shared__ float As[32][64];
    __shared__ float Bs[32][64];
    int bm = blockIdx.y * 64, bn = blockIdx.x * 64;
    int z = blockIdx.z;
    float* C = g_qp_part + z * (NTOK * 192);
    int tid = threadIdx.x, tx = tid & 15, ty = tid >> 4;
    float acc[4][4] = {};
    for (int kk = z * 64; kk < z * 64 + 64; kk += 32) {
#pragma unroll
        for (int i = 0; i < 2; ++i) {
            int t = tid + i * 256;
            int row = t >> 3;
            int c4 = (t & 7) * 4;
            float4 va = *(const float4*)(A + (size_t)(bm + row) * 512 + kk + c4);
            As[c4 + 0][row] = va.x; As[c4 + 1][row] = va.y;
            As[c4 + 2][row] = va.z; As[c4 + 3][row] = va.w;
            float4 vb = *(const float4*)(B + (size_t)(bn + row) * 512 + kk + c4);
            Bs[c4 + 0][row] = vb.x; Bs[c4 + 1][row] = vb.y;
            Bs[c4 + 2][row] = vb.z; Bs[c4 + 3][row] = vb.w;
        }
        __syncthreads();
#pragma unroll 8
        for (int k = 0; k < 32; ++k) {
            float4 a = *(const float4*)&As[k][ty * 4];
            float4 b = *(const float4*)&Bs[k][tx * 4];
            float av[4] = {a.x, a.y, a.z, a.w};
            float bv[4] = {b.x, b.y, b.z, b.w};
#pragma unroll
            for (int i = 0; i < 4; ++i)
#pragma unroll
                for (int j = 0; j < 4; ++j)
                    acc[i][j] = fmaf(av[i], bv[j], acc[i][j]);
        }
        __syncthreads();
    }
#pragma unroll
    for (int i = 0; i < 4; ++i) {
        float4 o = make_float4(acc[i][0], acc[i][1], acc[i][2], acc[i][3]);
        *(float4*)(C + (size_t)(bm + ty * 4 + i) * 192 + bn + tx * 4) = o;
    }
}

// ---------------------------------------------------------------------------
// z kernel: sum 8 split-K partials (all loads batched), __cosf prefix
// products, apply M to q-stream. grid 192 x 128.
// ---------------------------------------------------------------------------
__global__ __launch_bounds__(128) void k_z() {
    __shared__ float sM[64];
    __shared__ float sct[8];
    int t = threadIdx.x;
    if (t < 64) sM[t] = g_M[t];
    else if (t < 72) sct[t - 64] = g_ct[t - 64];
    __syncthreads();

    int idx = blockIdx.x * 128 + t;
    int n = idx / 24;
    int slot = idx - n * 24;
    int stream = slot >> 3;
    int h = slot & 7;
    int base = n * 192 + stream * 64 + h * 8;

    float4 u[KSPLIT], v[KSPLIT];
#pragma unroll
    for (int p = 0; p < KSPLIT; ++p) {
        u[p] = *(const float4*)(g_qp_part + p * (NTOK * 192) + base);
        v[p] = *(const float4*)(g_qp_part + p * (NTOK * 192) + base + 4);
    }
    float ang[8] = {};
#pragma unroll
    for (int p = 0; p < KSPLIT; ++p) {
        ang[0] += u[p].x; ang[1] += u[p].y; ang[2] += u[p].z; ang[3] += u[p].w;
        ang[4] += v[p].x; ang[5] += v[p].y; ang[6] += v[p].z; ang[7] += v[p].w;
    }

    float cz[8];
#pragma unroll
    for (int w = 0; w < 8; ++w) cz[w] = __cosf(ang[w]) * sct[w];
    float z[8];
    float p = 1.f;
#pragma unroll
    for (int w = 0; w < 8; ++w) { p *= cz[w]; z[w] = p; }

    float y[8];
    if (stream == 0) {
#pragma unroll
        for (int j = 0; j < 8; ++j) {
            float acc = 0.f;
#pragma unroll
            for (int i = 0; i < 8; ++i)
                acc = fmaf(z[i], sM[i * 8 + j], acc);
            y[j] = acc;
        }
    } else {
#pragma unroll
        for (int j = 0; j < 8; ++j) y[j] = z[j];
    }
    int b = n >> 9, s = n & 511;
    float* dst = g_z + ((size_t)(stream * 16 + b * 8 + h) * 512 + s) * 8;
    *(float4*)dst = make_float4(y[0], y[1], y[2], y[3]);
    *(float4*)(dst + 4) = make_float4(y[4], y[5], y[6], y[7]);
}

// ---------------------------------------------------------------------------
// Rank-8 attention, 4-way key split (no-max softmax -> partials combinable).
// grid (16 qt, 16 bh, 4 ks) = 1024 blocks, 128 threads = (rowgroup of 2
// rows, sub 0..7; 16 keys each). Q scaled by log2(e) -> raw ex2.approx.
// Writes partial (sum p*v, sum p); normalization folded into final GEMM.
// ---------------------------------------------------------------------------
__global__ __launch_bounds__(128) void k_attn8() {
    __shared__ float s_zk[128 * 12];
    __shared__ float s_zv[128 * 12];
    int qt = blockIdx.x, bh = blockIdx.y, ks = blockIdx.z;
    int b = bh >> 3, h = bh & 7;
    int q0 = qt * 32;
    int key0 = ks * 128;
    const float* gzq = g_z + (size_t)bh * 4096;
    const float* gzk = g_z + (size_t)(16 + bh) * 4096 + key0 * 8;
    const float* gzv = g_z + (size_t)(32 + bh) * 4096 + key0 * 8;
    int tid = threadIdx.x;

    {
        int r = tid;   // one key row per thread (128 rows)
        float4 a = ((const float4*)gzk)[r * 2], c = ((const float4*)gzk)[r * 2 + 1];
        *(float4*)(s_zk + r * 12) = a;
        *(float4*)(s_zk + r * 12 + 4) = c;
        float4 e = ((const float4*)gzv)[r * 2], f = ((const float4*)gzv)[r * 2 + 1];
        *(float4*)(s_zv + r * 12) = e;
        *(float4*)(s_zv + r * 12 + 4) = f;
    }
    __syncthreads();

    int rg = tid >> 3, sub = tid & 7;
    int r0 = q0 + rg * 2;
    const float L2E = 1.4426950408889634f;
    float y0[8], y1[8];
    {
        float4 a = ((const float4*)gzq)[r0 * 2], bq = ((const float4*)gzq)[r0 * 2 + 1];
        y0[0] = a.x * L2E; y0[1] = a.y * L2E; y0[2] = a.z * L2E; y0[3] = a.w * L2E;
        y0[4] = bq.x * L2E; y0[5] = bq.y * L2E; y0[6] = bq.z * L2E; y0[7] = bq.w * L2E;
        float4 c = ((const float4*)gzq)[(r0 + 1) * 2], e = ((const float4*)gzq)[(r0 + 1) * 2 + 1];
        y1[0] = c.x * L2E; y1[1] = c.y * L2E; y1[2] = c.z * L2E; y1[3] = c.w * L2E;
        y1[4] = e.x * L2E; y1[5] = e.y * L2E; y1[6] = e.z * L2E; y1[7] = e.w * L2E;
    }

    float l0 = 0.f, l1 = 0.f;
    float acc0[8] = {}, acc1[8] = {};
#pragma unroll 4
    for (int it = 0; it < 16; ++it) {
        int key = sub + it * 8;
        float4 k0 = *(const float4*)(s_zk + key * 12);
        float4 k1 = *(const float4*)(s_zk + key * 12 + 4);
        float kr[8] = {k0.x, k0.y, k0.z, k0.w, k1.x, k1.y, k1.z, k1.w};
        float s0 = y0[0] * kr[0], s1 = y1[0] * kr[0];
#pragma unroll
        for (int j = 1; j < 8; ++j) {
            s0 = fmaf(y0[j], kr[j], s0);
            s1 = fmaf(y1[j], kr[j], s1);
        }
        float p0 = ex2(s0), p1 = ex2(s1);
        l0 += p0; l1 += p1;
        float4 v0 = *(const float4*)(s_zv + key * 12);
        float4 v1 = *(const float4*)(s_zv + key * 12 + 4);
        float vr[8] = {v0.x, v0.y, v0.z, v0.w, v1.x, v1.y, v1.z, v1.w};
#pragma unroll
        for (int j = 0; j < 8; ++j) {
            acc0[j] = fmaf(p0, vr[j], acc0[j]);
            acc1[j] = fmaf(p1, vr[j], acc1[j]);
        }
    }
#pragma unroll
    for (int d = 1; d <= 4; d <<= 1) {
        l0 += __shfl_xor_sync(0xffffffffu, l0, d);
        l1 += __shfl_xor_sync(0xffffffffu, l1, d);
#pragma unroll
        for (int j = 0; j < 8; ++j) {
            acc0[j] += __shfl_xor_sync(0xffffffffu, acc0[j], d);
            acc1[j] += __shfl_xor_sync(0xffffffffu, acc1[j], d);
        }
    }
    if (sub == 0) {
        int n0 = b * 512 + r0;
        float* yp = g_Yp + ks * (NTOK * 64);
        float* lp = g_lp + ks * (NTOK * 8);
        float4* o = (float4*)(yp + (size_t)n0 * 64 + h * 8);
        o[0] = make_float4(acc0[0], acc0[1], acc0[2], acc0[3]);
        o[1] = make_float4(acc0[4], acc0[5], acc0[6], acc0[7]);
        float4* o2 = (float4*)(yp + (size_t)(n0 + 1) * 64 + h * 8);
        o2[0] = make_float4(acc1[0], acc1[1], acc1[2], acc1[3]);
        o2[1] = make_float4(acc1[4], acc1[5], acc1[6], acc1[7]);
        lp[n0 * 8 + h] = l0;
        lp[(n0 + 1) * 8 + h] = l1;
    }
}

// ---------------------------------------------------------------------------
// Final GEMM: out = Y(1024x64) @ U(512x64)^T, Y assembled on the fly from
// 4 key-split partials: Y = (sum Yp)/(sum lp). Tile 64(M)x64(N), BK=64
// (single sync), grid (8, 16) = 128 blocks, 256 threads, 4x4 microtile.
// All assembly loads batched for MLP.
// ---------------------------------------------------------------------------
__global__ __launch_bounds__(256) void k_gemm_fin(float* __restrict__ C) {
    __shared__ float As[64][64];   // [k][m]
    __shared__ float Bs[64][64];   // [k][n]
    int bm = blockIdx.y * 64, bn = blockIdx.x * 64;
    int tid = threadIdx.x;
    int tx = tid & 15, ty = tid >> 4;

    // Assemble A tile: 64 rows x 64 cols. Thread: row = tid>>2 (4 thr/row),
    // quarter qd = tid&3 covers cols qd*16..qd*16+15 (= heads 2qd, 2qd+1).
    {
        int r = tid >> 2, qd = tid & 3;
        int n = bm + r;
        int h0 = qd * 2;
        float l0 = 0.f, l1 = 0.f;
#pragma unroll
        for (int ks = 0; ks < AKS; ++ks) {
            l0 += g_lp[ks * (NTOK * 8) + n * 8 + h0];
            l1 += g_lp[ks * (NTOK * 8) + n * 8 + h0 + 1];
        }
        float inv0 = 1.f / l0, inv1 = 1.f / l1;
#pragma unroll
        for (int j = 0; j < 4; ++j) {
            int c4 = qd * 16 + j * 4;
            float sx = 0.f, sy = 0.f, sz = 0.f, sw = 0.f;
#pragma unroll
            for (int ks = 0; ks < AKS; ++ks) {
                float4 p = *(const float4*)(g_Yp + (size_t)ks * (NTOK * 64) + n * 64 + c4);
                sx += p.x; sy += p.y; sz += p.z; sw += p.w;
            }
            float inv = (j < 2) ? inv0 : inv1;
            As[c4 + 0][r] = sx * inv;
            As[c4 + 1][r] = sy * inv;
            As[c4 + 2][r] = sz * inv;
            As[c4 + 3][r] = sw * inv;
        }
    }
    // B tile: 64 rows x 64 k = 4096 floats, 4 float4/thread
#pragma unroll
    for (int i = 0; i < 4; ++i) {
        int t = tid + i * 256;
        int row = t >> 4;
        int c4 = (t & 15) * 4;
        float4 v = *(const float4*)(g_U + (size_t)(bn + row) * 64 + c4);
        Bs[c4 + 0][row] = v.x; Bs[c4 + 1][row] = v.y;
        Bs[c4 + 2][row] = v.z; Bs[c4 + 3][row] = v.w;
    }
    __syncthreads();

    float acc[4][4] = {};
#pragma unroll 8
    for (int k = 0; k < 64; ++k) {
        float4 a = *(const float4*)&As[k][ty * 4];
        float4 b = *(const float4*)&Bs[k][tx * 4];
        float av[4] = {a.x, a.y, a.z, a.w};
        float bv[4] = {b.x, b.y, b.z, b.w};
#pragma unroll
        for (int i = 0; i < 4; ++i)
#pragma unroll
            for (int j = 0; j < 4; ++j)
                acc[i][j] = fmaf(av[i], bv[j], acc[i][j]);
    }
#pragma unroll
    for (int i = 0; i < 4; ++i) {
        float4 o = make_float4(acc[i][0], acc[i][1], acc[i][2], acc[i][3]);
        *(float4*)(C + (size_t)(bm + ty * 4 + i) * 512 + bn + tx * 4) = o;
    }
}

// ---------------------------------------------------------------------------
extern "C" void kernel_launch(void* const* d_in, const int* in_sizes, int n_in,
                              void* d_out, int out_size) {
    const float* x      = (const float*)d_in[0];
    const float* Wq     = (const float*)d_in[1];
    const float* Wk     = (const float*)d_in[2];
    const float* Wv     = (const float*)d_in[3];
    const float* Wo     = (const float*)d_in[4];
    const float* Pin_q  = (const float*)d_in[5];
    const float* Pin_k  = (const float*)d_in[6];
    const float* Pin_v  = (const float*)d_in[7];
    const float* Pout_q = (const float*)d_in[8];
    const float* Pout_k = (const float*)d_in[9];
    const float* Pout_v = (const float*)d_in[10];
    const float* theta  = (const float*)d_in[11];
    float* out = (float*)d_out;

    k_fold<<<65, 256>>>(Wq, Wk, Wv, Wo, Pin_q, Pin_k, Pin_v,
                        Pout_q, Pout_k, Pout_v, theta);
    k_gemm_qp<<<dim3(3, 16, KSPLIT), 256>>>(x);
    k_z<<<192, 128>>>();
    k_attn8<<<dim3(16, 16, AKS), 128>>>();
    k_gemm_fin<<<dim3(8, 16), 256>>>(out);
}